// round 4
// baseline (speedup 1.0000x reference)
#include <cuda_runtime.h>

// Problem constants
#define NQ   20
#define NL   8
#define BB   32
#define DIM  (1u << NQ)        // 1048576
#define NF4  (DIM / 4)         // 262144 float4s per statevector

// Fused-kernel geometry: 512 blocks x 128 threads, 4 float4/thread.
// f4 index f = c*512 + u*128 + t ; element i = 4f + r.
//   i bits 0,1   <- r (float4 lane)
//   i bits 2..8  <- t (7 bits, deferred to end-of-block combine via smem)
//   i bits 9,10  <- u (compile-time predicated adds)
//   i bits 11..19<- c (free, applied in combine)
#define TPB   128
#define CH    512                    // chunks = blocks
#define U     4                      // float4 per thread
#define F4PB  (TPB * U)              // 512 float4 per block

// Scratch: per-(chunk,batch) 21 partial sums. 512*32*21 floats = 1.38 MB.
__device__ float g_part[CH * BB * 21];

// ---------------------------------------------------------------------------
// Fused kernel: compute G slice in registers, sweep all 32 batches.
// ---------------------------------------------------------------------------
__global__ void __launch_bounds__(TPB) k_fused(const float* __restrict__ noise,
                                               const float* __restrict__ amps) {
    const int c    = blockIdx.x;
    const int t    = threadIdx.x;
    const int lane = t & 31, warp = t >> 5;

    const size_t base = (size_t)c * F4PB + t;
    const float4* n4 = reinterpret_cast<const float4*>(noise);
    const float4* a4 = reinterpret_cast<const float4*>(amps);

    // ---- Phase 1: G slice in registers (32 independent loads in flight) ----
    float4 G[U];
#pragma unroll
    for (int u = 0; u < U; u++) {
        float4 v = __ldcs(n4 + base + u * TPB);
        G[u].x = v.x * v.x; G[u].y = v.y * v.y;
        G[u].z = v.z * v.z; G[u].w = v.w * v.w;
    }
#pragma unroll
    for (int l = 1; l < NL; l++) {
#pragma unroll
        for (int u = 0; u < U; u++) {
            float4 v = __ldcs(n4 + (size_t)l * NF4 + base + u * TPB);
            G[u].x *= v.x * v.x; G[u].y *= v.y * v.y;
            G[u].z *= v.z * v.z; G[u].w *= v.w * v.w;
        }
    }

    __shared__ float sT[BB][TPB];      // per-thread totals (thread-bit qubits)
    __shared__ float red4[BB][4][4];   // warp-reduced acc0, acc1, aU0, aU1

    // ---- Phase 2: sweep batches ----
    for (int b = 0; b < BB; b++) {
        float acc0 = 0.f, acc1 = 0.f, aU0 = 0.f, aU1 = 0.f, aT = 0.f;
        const float4* ab = a4 + (size_t)b * NF4 + base;
#pragma unroll
        for (int u = 0; u < U; u++) {
            float4 a = __ldcs(ab + u * TPB);
            float w0 = a.x * a.x * G[u].x;
            float w1 = a.y * a.y * G[u].y;
            float w2 = a.z * a.z * G[u].z;
            float w3 = a.w * a.w * G[u].w;
            float s  = (w0 + w1) + (w2 + w3);
            acc0 += w1 + w3;            // i bit 0
            acc1 += w2 + w3;            // i bit 1
            if (u & 1) aU0 += s;        // i bit 9  (compile-time)
            if (u & 2) aU1 += s;        // i bit 10 (compile-time)
            aT += s;
        }
#pragma unroll
        for (int o = 16; o > 0; o >>= 1) {
            acc0 += __shfl_xor_sync(0xffffffffu, acc0, o);
            acc1 += __shfl_xor_sync(0xffffffffu, acc1, o);
            aU0  += __shfl_xor_sync(0xffffffffu, aU0, o);
            aU1  += __shfl_xor_sync(0xffffffffu, aU1, o);
        }
        if (lane == 0) {
            red4[b][warp][0] = acc0; red4[b][warp][1] = acc1;
            red4[b][warp][2] = aU0;  red4[b][warp][3] = aU1;
        }
        sT[b][t] = aT;
    }
    __syncthreads();

    // ---- Phase 3: combine. Warp w handles batches w*8 .. w*8+7. ----
    for (int bb = 0; bb < 8; bb++) {
        const int b = warp * 8 + bb;
        // lane covers original threads t' = lane*4 + j, j<4
        float v0 = sT[b][lane * 4 + 0];
        float v1 = sT[b][lane * 4 + 1];
        float v2 = sT[b][lane * 4 + 2];
        float v3 = sT[b][lane * 4 + 3];
        float tt = (v0 + v1) + (v2 + v3);
        float m[7];
        m[0] = v1 + v3;                          // t' bit 0  -> i bit 2
        m[1] = v2 + v3;                          // t' bit 1  -> i bit 3
#pragma unroll
        for (int k = 0; k < 5; k++)              // t' bits 2..6 -> i bits 4..8
            m[2 + k] = ((lane >> k) & 1) ? tt : 0.f;
#pragma unroll
        for (int o = 16; o > 0; o >>= 1) {
            tt += __shfl_xor_sync(0xffffffffu, tt, o);
#pragma unroll
            for (int k = 0; k < 7; k++)
                m[k] += __shfl_xor_sync(0xffffffffu, m[k], o);
        }
        if (lane == 0) {
            float q[21];
            q[0] = red4[b][0][0] + red4[b][1][0] + red4[b][2][0] + red4[b][3][0];
            q[1] = red4[b][0][1] + red4[b][1][1] + red4[b][2][1] + red4[b][3][1];
#pragma unroll
            for (int k = 0; k < 7; k++) q[2 + k] = m[k];
            q[9]  = red4[b][0][2] + red4[b][1][2] + red4[b][2][2] + red4[b][3][2];
            q[10] = red4[b][0][3] + red4[b][1][3] + red4[b][2][3] + red4[b][3][3];
#pragma unroll
            for (int k = 0; k < 9; k++)          // i bits 11..19 <- chunk bits
                q[11 + k] = ((c >> k) & 1) ? tt : 0.f;
            q[20] = tt;
            float* dst = &g_part[((size_t)c * BB + b) * 21];
#pragma unroll
            for (int k = 0; k < 21; k++) dst[k] = q[k];
        }
    }
}

// ---------------------------------------------------------------------------
// Final kernel: one block per batch. Reduce 512 chunk-partials, then
// tanh(qp @ Wi + bi).
// ---------------------------------------------------------------------------
__global__ void __launch_bounds__(128) k_final(const float* __restrict__ Wi,
                                               const float* __restrict__ bi,
                                               float* __restrict__ out) {
    const int b = blockIdx.x;
    const int t = threadIdx.x;

    float part[21];
#pragma unroll
    for (int k = 0; k < 21; k++) part[k] = 0.f;
#pragma unroll
    for (int cc = 0; cc < CH / 128; cc++) {
        const float* p = &g_part[((size_t)(t + cc * 128) * BB + b) * 21];
#pragma unroll
        for (int k = 0; k < 21; k++) part[k] += p[k];
    }

    __shared__ float sm[128][21];
#pragma unroll
    for (int k = 0; k < 21; k++) sm[t][k] = part[k];
    __syncthreads();

    __shared__ float Q[21];
    if (t < 21) {
        float s = 0.f;
        for (int w = 0; w < 128; w++) s += sm[w][t];
        Q[t] = s;
    }
    __syncthreads();

    if (t < NQ) {
        const float inv = 1.f / Q[20];
        float acc = bi[t];
#pragma unroll
        for (int q = 0; q < NQ; q++) acc += (Q[q] * inv) * Wi[q * NQ + t];
        out[b * NQ + t] = tanhf(acc);
    }
}

// ---------------------------------------------------------------------------
// Launch: 2 graph-capturable kernels, no syncs, no allocations.
// ---------------------------------------------------------------------------
extern "C" void kernel_launch(void* const* d_in, const int* in_sizes, int n_in,
                              void* d_out, int out_size) {
    int i_amps = 7, i_noise = 8, i_Wi = 9, i_bi = 10;
    for (int i = 0; i < n_in; i++) {
        const long sz = in_sizes[i];
        if (sz == (long)BB * (long)DIM)      i_amps  = i;  // 33,554,432
        else if (sz == (long)NL * (long)DIM) i_noise = i;  //  8,388,608
        else if (sz == NQ * NQ)              i_Wi    = i;  // 400
        else if (sz == NQ)                   i_bi    = i;  // 20
    }

    const float* noise = (const float*)d_in[i_noise];
    const float* amps  = (const float*)d_in[i_amps];
    const float* Wi    = (const float*)d_in[i_Wi];
    const float* bi    = (const float*)d_in[i_bi];
    float* out         = (float*)d_out;

    k_fused<<<CH, TPB>>>(noise, amps);     // 512 blocks, 128 threads
    k_final<<<BB, 128>>>(Wi, bi, out);     // 32 blocks (one per batch)
}

// round 5
// speedup vs baseline: 1.3684x; 1.3684x over previous
#include <cuda_runtime.h>

// Problem constants
#define NQ   20
#define NL   8
#define BB   32
#define DIM  (1u << NQ)        // 1048576
#define NF4  (DIM / 4)         // 262144 float4s per statevector
#define TPB  256

// K2 geometry: 64 chunks x 16 batch-groups (2 batches each) = 1024 blocks
#define CHUNKS 64
#define BPG 2                          // batches per block
#define NGRP (BB / BPG)                // 16 batch groups
#define F4_PER_CHUNK (NF4 / CHUNKS)    // 4096 float4 per chunk
#define JI 16                          // inner iters (bits 10..13); JI*TPB == F4_PER_CHUNK

// Scratch (static device arrays: no allocation anywhere)
__device__ float g_G[DIM];                                // G[i] = prod_l noise[l,i]^2
__device__ float g_part[CHUNKS * NGRP * BPG * 21];        // per-block partials

// ---------------------------------------------------------------------------
// Kernel 1: G[i] = prod over 8 layers of noise[l,i]^2.
// All 8 loads issued into an explicit register array BEFORE any math so ptxas
// cannot recycle the load registers -> 8 LDG.128 genuinely in flight.
// ---------------------------------------------------------------------------
__global__ void __launch_bounds__(TPB) k_prodG(const float* __restrict__ noise) {
    const unsigned i = blockIdx.x * TPB + threadIdx.x;    // grid covers NF4 exactly
    const float4* n4 = reinterpret_cast<const float4*>(noise);

    float4 v[NL];
#pragma unroll
    for (int l = 0; l < NL; l++)
        v[l] = __ldcs(n4 + (size_t)l * NF4 + i);

    // pairwise tree to keep FMA ILP
    float4 p[4];
#pragma unroll
    for (int k = 0; k < 4; k++) {
        p[k].x = (v[2*k].x * v[2*k].x) * (v[2*k+1].x * v[2*k+1].x);
        p[k].y = (v[2*k].y * v[2*k].y) * (v[2*k+1].y * v[2*k+1].y);
        p[k].z = (v[2*k].z * v[2*k].z) * (v[2*k+1].z * v[2*k+1].z);
        p[k].w = (v[2*k].w * v[2*k].w) * (v[2*k+1].w * v[2*k+1].w);
    }
    float4 g;
    g.x = (p[0].x * p[1].x) * (p[2].x * p[3].x);
    g.y = (p[0].y * p[1].y) * (p[2].y * p[3].y);
    g.z = (p[0].z * p[1].z) * (p[2].z * p[3].z);
    g.w = (p[0].w * p[1].w) * (p[2].w * p[3].w);
    reinterpret_cast<float4*>(g_G)[i] = g;
}

// ---------------------------------------------------------------------------
// Kernel 2: bit-masked reduction, 2 batches per block, 1024 blocks.
// Element index i = idx*4 + r;  idx = chunk*4096 + ji*256 + t.
//   qubits 0,1   <- r          (per-float4 lane position)
//   qubits 2..9  <- t bits     (free: applied at reduction time)
//   qubits 10..13<- ji bits    (compile-time predicated adds)
//   qubits 14..19<- chunk bits (free: applied at reduction time)
// ---------------------------------------------------------------------------
__global__ void __launch_bounds__(TPB) k_bitsum(const float* __restrict__ amps) {
    const int bg    = blockIdx.x & (NGRP - 1);   // batch group: batches bg*2, bg*2+1
    const int chunk = blockIdx.x >> 4;           // 0..63
    const int t     = threadIdx.x;

    const size_t sliceOff = (size_t)chunk * F4_PER_CHUNK + t;
    const float4* g4   = reinterpret_cast<const float4*>(g_G) + sliceOff;
    const float4* a4_0 = reinterpret_cast<const float4*>(amps)
                         + (size_t)(bg * BPG + 0) * NF4 + sliceOff;
    const float4* a4_1 = reinterpret_cast<const float4*>(amps)
                         + (size_t)(bg * BPG + 1) * NF4 + sliceOff;

    float acc0[BPG]  = {0.f, 0.f}, acc1[BPG]  = {0.f, 0.f};
    float accJ0[BPG] = {0.f, 0.f}, accJ1[BPG] = {0.f, 0.f};
    float accJ2[BPG] = {0.f, 0.f}, accJ3[BPG] = {0.f, 0.f};
    float accT[BPG]  = {0.f, 0.f};

#pragma unroll
    for (int ji = 0; ji < JI; ji++) {
        const int off = ji * TPB;
        float4 g  = __ldg(g4 + off);           // hot in L2, shared by 16 blocks
        float4 a0 = __ldcs(a4_0 + off);        // streaming, read-once
        float4 a1 = __ldcs(a4_1 + off);
#pragma unroll
        for (int b2 = 0; b2 < BPG; b2++) {
            float4 a = b2 ? a1 : a0;
            float w0 = a.x * a.x * g.x;
            float w1 = a.y * a.y * g.y;
            float w2 = a.z * a.z * g.z;
            float w3 = a.w * a.w * g.w;
            float s  = (w0 + w1) + (w2 + w3);
            acc0[b2] += w1 + w3;               // qubit 0
            acc1[b2] += w2 + w3;               // qubit 1
            if (ji & 1) accJ0[b2] += s;        // qubit 10 (folded at compile time)
            if (ji & 2) accJ1[b2] += s;        // qubit 11
            if (ji & 4) accJ2[b2] += s;        // qubit 12
            if (ji & 8) accJ3[b2] += s;        // qubit 13
            accT[b2] += s;
        }
    }

    __shared__ float red[TPB / 32][BPG][21];
    const int wid = t >> 5, lane = t & 31;

#pragma unroll
    for (int b2 = 0; b2 < BPG; b2++) {
        float vals[21];
        vals[0] = acc0[b2];
        vals[1] = acc1[b2];
#pragma unroll
        for (int k = 0; k < 8; k++) vals[2 + k] = ((t >> k) & 1) ? accT[b2] : 0.f;
        vals[10] = accJ0[b2]; vals[11] = accJ1[b2];
        vals[12] = accJ2[b2]; vals[13] = accJ3[b2];
#pragma unroll
        for (int m = 0; m < 6; m++) vals[14 + m] = ((chunk >> m) & 1) ? accT[b2] : 0.f;
        vals[20] = accT[b2];
#pragma unroll
        for (int k = 0; k < 21; k++) {
#pragma unroll
            for (int o = 16; o > 0; o >>= 1)
                vals[k] += __shfl_xor_sync(0xffffffffu, vals[k], o);
        }
        if (lane == 0) {
#pragma unroll
            for (int k = 0; k < 21; k++) red[wid][b2][k] = vals[k];
        }
    }
    __syncthreads();
    if (t < BPG * 21) {
        const int b2 = t / 21, k = t % 21;
        float s = 0.f;
#pragma unroll
        for (int w = 0; w < TPB / 32; w++) s += red[w][b2][k];
        g_part[(size_t)blockIdx.x * (BPG * 21) + t] = s;
    }
}

// ---------------------------------------------------------------------------
// Kernel 3: reduce partials -> qubit probs -> tanh(qp @ Wi + bi)
// ---------------------------------------------------------------------------
__global__ void k_final(const float* __restrict__ Wi, const float* __restrict__ bi,
                        float* __restrict__ out) {
    __shared__ float Q[BB][21];
    const int t = threadIdx.x;
    if (t < BB * 21) {
        const int b = t / 21, k = t % 21;
        const int bg = b >> 1, b2 = b & 1;
        float s = 0.f;
#pragma unroll
        for (int c = 0; c < CHUNKS; c++)
            s += g_part[(size_t)(c * NGRP + bg) * (BPG * 21) + b2 * 21 + k];
        Q[b][k] = s;
    }
    __syncthreads();
    if (t < BB * NQ) {
        const int b = t / NQ, j = t % NQ;
        const float inv = 1.f / Q[b][20];
        float acc = bi[j];
#pragma unroll
        for (int q = 0; q < NQ; q++) acc += (Q[b][q] * inv) * Wi[q * NQ + j];
        out[t] = tanhf(acc);
    }
}

// ---------------------------------------------------------------------------
// Launch: 3 graph-capturable kernels, no syncs, no allocations.
// ---------------------------------------------------------------------------
extern "C" void kernel_launch(void* const* d_in, const int* in_sizes, int n_in,
                              void* d_out, int out_size) {
    int i_amps = 7, i_noise = 8, i_Wi = 9, i_bi = 10;
    for (int i = 0; i < n_in; i++) {
        const long sz = in_sizes[i];
        if (sz == (long)BB * (long)DIM)      i_amps  = i;  // 33,554,432
        else if (sz == (long)NL * (long)DIM) i_noise = i;  //  8,388,608
        else if (sz == NQ * NQ)              i_Wi    = i;  // 400
        else if (sz == NQ)                   i_bi    = i;  // 20
    }

    const float* noise = (const float*)d_in[i_noise];
    const float* amps  = (const float*)d_in[i_amps];
    const float* Wi    = (const float*)d_in[i_Wi];
    const float* bi    = (const float*)d_in[i_bi];
    float* out         = (float*)d_out;

    k_prodG <<<NF4 / TPB, TPB>>>(noise);        // 1024 blocks, true MLP=8
    k_bitsum<<<CHUNKS * NGRP, TPB>>>(amps);     // 1024 blocks, 2 batches each
    k_final <<<1, BB * 21>>>(Wi, bi, out);      // 672 threads
}

// round 6
// speedup vs baseline: 1.6014x; 1.1702x over previous
#include <cuda_runtime.h>

// Problem constants
#define NQ   20
#define NL   8
#define BB   32
#define DIM  (1u << NQ)        // 1048576
#define NF4  (DIM / 4)         // 262144 float4s per statevector
#define TPB  256

// K2 geometry (R3, measured best): 32 chunks x 16 batch-groups = 512 blocks
#define CHUNKS 32
#define BPG 2
#define NGRP (BB / BPG)                // 16
#define F4_PER_CHUNK (NF4 / CHUNKS)    // 8192
#define NIT 32                         // flattened JO(2) * JI(16); NIT*TPB == F4_PER_CHUNK

// Scratch
__device__ float g_G[DIM];
__device__ float g_part[CHUNKS * NGRP * BPG * 21];

// Forced-issue vector loads (volatile: cannot be sunk past each other)
#define LDG_CS_F4(d, p)                                                     \
    asm volatile("ld.global.cs.v4.f32 {%0,%1,%2,%3}, [%4];"                 \
                 : "=f"((d).x), "=f"((d).y), "=f"((d).z), "=f"((d).w)       \
                 : "l"(p))
#define LDG_CA_F4(d, p)                                                     \
    asm volatile("ld.global.v4.f32 {%0,%1,%2,%3}, [%4];"                    \
                 : "=f"((d).x), "=f"((d).y), "=f"((d).z), "=f"((d).w)       \
                 : "l"(p))

// ---------------------------------------------------------------------------
// Kernel 1: G[i] = prod_l noise[l,i]^2. All 8 loads issued via volatile asm
// before any math -> true MLP=8 per thread.
// ---------------------------------------------------------------------------
__global__ void __launch_bounds__(TPB) k_prodG(const float* __restrict__ noise) {
    const unsigned i = blockIdx.x * TPB + threadIdx.x;
    const float4* n4 = reinterpret_cast<const float4*>(noise);

    float4 v0, v1, v2, v3, v4, v5, v6, v7;
    LDG_CS_F4(v0, n4 + 0 * (size_t)NF4 + i);
    LDG_CS_F4(v1, n4 + 1 * (size_t)NF4 + i);
    LDG_CS_F4(v2, n4 + 2 * (size_t)NF4 + i);
    LDG_CS_F4(v3, n4 + 3 * (size_t)NF4 + i);
    LDG_CS_F4(v4, n4 + 4 * (size_t)NF4 + i);
    LDG_CS_F4(v5, n4 + 5 * (size_t)NF4 + i);
    LDG_CS_F4(v6, n4 + 6 * (size_t)NF4 + i);
    LDG_CS_F4(v7, n4 + 7 * (size_t)NF4 + i);

    float4 g;
    g.x = ((v0.x*v0.x)*(v1.x*v1.x)) * ((v2.x*v2.x)*(v3.x*v3.x))
        * (((v4.x*v4.x)*(v5.x*v5.x)) * ((v6.x*v6.x)*(v7.x*v7.x)));
    g.y = ((v0.y*v0.y)*(v1.y*v1.y)) * ((v2.y*v2.y)*(v3.y*v3.y))
        * (((v4.y*v4.y)*(v5.y*v5.y)) * ((v6.y*v6.y)*(v7.y*v7.y)));
    g.z = ((v0.z*v0.z)*(v1.z*v1.z)) * ((v2.z*v2.z)*(v3.z*v3.z))
        * (((v4.z*v4.z)*(v5.z*v5.z)) * ((v6.z*v6.z)*(v7.z*v7.z)));
    g.w = ((v0.w*v0.w)*(v1.w*v1.w)) * ((v2.w*v2.w)*(v3.w*v3.w))
        * (((v4.w*v4.w)*(v5.w*v5.w)) * ((v6.w*v6.w)*(v7.w*v7.w)));
    reinterpret_cast<float4*>(g_G)[i] = g;
}

// ---------------------------------------------------------------------------
// Kernel 2: bit-masked reduction (R3 geometry) + register double-buffer.
// Element index i = idx*4 + r;  idx = chunk*8192 + j*256 + t  (j = jo*16+ji).
//   qubits 0,1   <- r       qubits 2..9  <- t bits (at reduction)
//   qubits 10..13<- j&15    qubit 14     <- j>>4
//   qubits 15..19<- chunk bits (at reduction)
// ---------------------------------------------------------------------------
__global__ void __launch_bounds__(TPB) k_bitsum(const float* __restrict__ amps) {
    const int bg    = blockIdx.x & (NGRP - 1);
    const int chunk = blockIdx.x >> 4;
    const int t     = threadIdx.x;

    const size_t sliceOff = (size_t)chunk * F4_PER_CHUNK + t;
    const float4* g4   = reinterpret_cast<const float4*>(g_G) + sliceOff;
    const float4* a4_0 = reinterpret_cast<const float4*>(amps)
                         + (size_t)(bg * BPG + 0) * NF4 + sliceOff;
    const float4* a4_1 = reinterpret_cast<const float4*>(amps)
                         + (size_t)(bg * BPG + 1) * NF4 + sliceOff;

    float acc0[BPG]  = {0.f, 0.f}, acc1[BPG]  = {0.f, 0.f};
    float accJ0[BPG] = {0.f, 0.f}, accJ1[BPG] = {0.f, 0.f};
    float accJ2[BPG] = {0.f, 0.f}, accJ3[BPG] = {0.f, 0.f};
    float accO[BPG]  = {0.f, 0.f}, accT[BPG]  = {0.f, 0.f};

    float4 gC, a0C, a1C, gN, a0N, a1N;
    LDG_CA_F4(gC,  g4);
    LDG_CS_F4(a0C, a4_0);
    LDG_CS_F4(a1C, a4_1);

#pragma unroll
    for (int j = 0; j < NIT; j++) {
        if (j + 1 < NIT) {                     // issue next iter's loads FIRST
            const int off = (j + 1) * TPB;
            LDG_CA_F4(gN,  g4 + off);
            LDG_CS_F4(a0N, a4_0 + off);
            LDG_CS_F4(a1N, a4_1 + off);
        }
#pragma unroll
        for (int b2 = 0; b2 < BPG; b2++) {
            float4 a = b2 ? a1C : a0C;
            float w0 = a.x * a.x * gC.x;
            float w1 = a.y * a.y * gC.y;
            float w2 = a.z * a.z * gC.z;
            float w3 = a.w * a.w * gC.w;
            float s  = (w0 + w1) + (w2 + w3);
            acc0[b2] += w1 + w3;               // qubit 0
            acc1[b2] += w2 + w3;               // qubit 1
            if (j & 1)  accJ0[b2] += s;        // qubit 10 (compile-time)
            if (j & 2)  accJ1[b2] += s;        // qubit 11
            if (j & 4)  accJ2[b2] += s;        // qubit 12
            if (j & 8)  accJ3[b2] += s;        // qubit 13
            if (j & 16) accO[b2]  += s;        // qubit 14
            accT[b2] += s;
        }
        gC = gN; a0C = a0N; a1C = a1N;
    }

    __shared__ float red[TPB / 32][BPG][21];
    const int wid = t >> 5, lane = t & 31;

#pragma unroll
    for (int b2 = 0; b2 < BPG; b2++) {
        float vals[21];
        vals[0] = acc0[b2];
        vals[1] = acc1[b2];
#pragma unroll
        for (int k = 0; k < 8; k++) vals[2 + k] = ((t >> k) & 1) ? accT[b2] : 0.f;
        vals[10] = accJ0[b2]; vals[11] = accJ1[b2];
        vals[12] = accJ2[b2]; vals[13] = accJ3[b2];
        vals[14] = accO[b2];
#pragma unroll
        for (int m = 0; m < 5; m++) vals[15 + m] = ((chunk >> m) & 1) ? accT[b2] : 0.f;
        vals[20] = accT[b2];
#pragma unroll
        for (int k = 0; k < 21; k++) {
#pragma unroll
            for (int o = 16; o > 0; o >>= 1)
                vals[k] += __shfl_xor_sync(0xffffffffu, vals[k], o);
        }
        if (lane == 0) {
#pragma unroll
            for (int k = 0; k < 21; k++) red[wid][b2][k] = vals[k];
        }
    }
    __syncthreads();
    if (t < BPG * 21) {
        const int b2 = t / 21, k = t % 21;
        float s = 0.f;
#pragma unroll
        for (int w = 0; w < TPB / 32; w++) s += red[w][b2][k];
        g_part[(size_t)blockIdx.x * (BPG * 21) + t] = s;
    }
}

// ---------------------------------------------------------------------------
// Kernel 3: reduce partials -> qubit probs -> tanh(qp @ Wi + bi)
// ---------------------------------------------------------------------------
__global__ void k_final(const float* __restrict__ Wi, const float* __restrict__ bi,
                        float* __restrict__ out) {
    __shared__ float Q[BB][21];
    const int t = threadIdx.x;
    if (t < BB * 21) {
        const int b = t / 21, k = t % 21;
        const int bg = b >> 1, b2 = b & 1;
        float s = 0.f;
#pragma unroll
        for (int c = 0; c < CHUNKS; c++)
            s += g_part[(size_t)(c * NGRP + bg) * (BPG * 21) + b2 * 21 + k];
        Q[b][k] = s;
    }
    __syncthreads();
    if (t < BB * NQ) {
        const int b = t / NQ, j = t % NQ;
        const float inv = 1.f / Q[b][20];
        float acc = bi[j];
#pragma unroll
        for (int q = 0; q < NQ; q++) acc += (Q[b][q] * inv) * Wi[q * NQ + j];
        out[t] = tanhf(acc);
    }
}

// ---------------------------------------------------------------------------
// Launch
// ---------------------------------------------------------------------------
extern "C" void kernel_launch(void* const* d_in, const int* in_sizes, int n_in,
                              void* d_out, int out_size) {
    int i_amps = 7, i_noise = 8, i_Wi = 9, i_bi = 10;
    for (int i = 0; i < n_in; i++) {
        const long sz = in_sizes[i];
        if (sz == (long)BB * (long)DIM)      i_amps  = i;
        else if (sz == (long)NL * (long)DIM) i_noise = i;
        else if (sz == NQ * NQ)              i_Wi    = i;
        else if (sz == NQ)                   i_bi    = i;
    }

    const float* noise = (const float*)d_in[i_noise];
    const float* amps  = (const float*)d_in[i_amps];
    const float* Wi    = (const float*)d_in[i_Wi];
    const float* bi    = (const float*)d_in[i_bi];
    float* out         = (float*)d_out;

    k_prodG <<<NF4 / TPB, TPB>>>(noise);        // 1024 blocks, forced MLP=8
    k_bitsum<<<CHUNKS * NGRP, TPB>>>(amps);     //  512 blocks (R3 geometry) + prefetch
    k_final <<<1, BB * 21>>>(Wi, bi, out);
}